// round 13
// baseline (speedup 1.0000x reference)
#include <cuda_runtime.h>
#include <math_constants.h>

// Problem constants
#define BB 256
#define CC 8
#define MM 16
#define NN 4096
#define CM 128      // CC*MM
#define LEN_R 64
#define LEN_D 64
#define NBLK 4      // blocks along N per b (NN / 1024)

// Per-(b, n-block) partial argmax scratch + per-b ticket (device globals).
__device__ float g_pmax[BB][NBLK];
__device__ int   g_pidx[BB][NBLK];
__device__ int   g_ticket[BB];

// Fused kernel:
//  - outputs[b,n] = sum_k x[b,k,n] * W[k]  (k = c*M+m, 128 terms)
//  - streaming loads (__ldcs) / stores (__stcs): data touched exactly once
//  - warp-shuffle partial argmax (first occurrence) -> scratch
//  - last block per b reduces partials, writes tail, resets ticket.
// tail layout (after outputs): d[B], r[B], d[B] (pytree leaves of (outputs, d, (r,d)))
__global__ __launch_bounds__(256) void fused_kernel(
    const float* __restrict__ x, const float* __restrict__ W,
    const float* __restrict__ r_target, const float* __restrict__ d_target,
    float* __restrict__ out, float* __restrict__ tail)
{
    __shared__ float w[CM];
    int t = threadIdx.x;
    if (t < CM) w[t] = W[t];
    __syncthreads();

    int b  = blockIdx.y;
    int n4 = blockIdx.x * blockDim.x + t;          // float4 lane index in N/4
    const float4* xb = reinterpret_cast<const float4*>(x) + (size_t)b * CM * (NN / 4);

    float4 acc = make_float4(0.f, 0.f, 0.f, 0.f);
    #pragma unroll 16
    for (int k = 0; k < CM; k++) {
        float4 v = __ldcs(&xb[(size_t)k * (NN / 4) + n4]);   // evict-first stream
        float wk = w[k];
        acc.x += v.x * wk;
        acc.y += v.y * wk;
        acc.z += v.z * wk;
        acc.w += v.w * wk;
    }
    __stcs(&reinterpret_cast<float4*>(out + (size_t)b * NN)[n4], acc);

    // Thread-local argmax over 4 lanes (strict > keeps first occurrence).
    int nbase = n4 * 4;
    float best = acc.x; int bidx = nbase;
    if (acc.y > best) { best = acc.y; bidx = nbase + 1; }
    if (acc.z > best) { best = acc.z; bidx = nbase + 2; }
    if (acc.w > best) { best = acc.w; bidx = nbase + 3; }

    // Warp reduction via shuffles; lower lane holds lower index, so strict >
    // with (==, oi < bidx) keeps first occurrence.
    #pragma unroll
    for (int off = 16; off > 0; off >>= 1) {
        float ov = __shfl_down_sync(0xffffffffu, best, off);
        int   oi = __shfl_down_sync(0xffffffffu, bidx, off);
        if (ov > best || (ov == best && oi < bidx)) { best = ov; bidx = oi; }
    }

    // 8 warp leaders -> smem, one barrier, warp 0 finishes.
    __shared__ float sv[8];
    __shared__ int   si[8];
    int warp = t >> 5, lane = t & 31;
    if (lane == 0) { sv[warp] = best; si[warp] = bidx; }
    __syncthreads();

    __shared__ int s_last;
    if (warp == 0) {
        float fb = (lane < 8) ? sv[lane] : -CUDART_INF_F;
        int   fi = (lane < 8) ? si[lane] : NN;      // sentinel index
        #pragma unroll
        for (int off = 4; off > 0; off >>= 1) {
            float ov = __shfl_down_sync(0xffffffffu, fb, off);
            int   oi = __shfl_down_sync(0xffffffffu, fi, off);
            if (ov > fb || (ov == fb && oi < fi)) { fb = ov; fi = oi; }
        }
        if (lane == 0) {
            g_pmax[b][blockIdx.x] = fb;
            g_pidx[b][blockIdx.x] = fi;
            __threadfence();
            int prev = atomicAdd(&g_ticket[b], 1);
            s_last = (prev == NBLK - 1);
        }
    }
    __syncthreads();

    if (s_last && t == 0) {
        // Winner re-reads all partials; volatile forces L2-visible loads
        // (L1 is per-SM and non-coherent for plain global loads).
        volatile float* pm = &g_pmax[b][0];
        volatile int*   pi = &g_pidx[b][0];
        float fb = pm[0];
        int   fi = pi[0];
        #pragma unroll
        for (int j = 1; j < NBLK; j++) {
            float v = pm[j]; int i = pi[j];
            if (v > fb || (v == fb && i < fi)) { fb = v; fi = i; }
        }
        int ri = fi / LEN_R;
        int di = fi - (fi / LEN_R) * LEN_D;
        // .astype(index.dtype) truncates toward zero; replicate via int cast.
        float rv = (float)(long long)(r_target[ri]);
        float dv = (float)(long long)(d_target[di]);
        tail[b]          = dv;  // leaf 2: d
        tail[BB + b]     = rv;  // leaf 3: r
        tail[2 * BB + b] = dv;  // leaf 4: d
        g_ticket[b] = 0;       // reset for next graph replay (deterministic)
    }
}

extern "C" void kernel_launch(void* const* d_in, const int* in_sizes, int n_in,
                              void* d_out, int out_size)
{
    const float* x  = (const float*)d_in[0];  // [B, C, M, N]
    const float* W  = (const float*)d_in[1];  // [1, C, M, 1] -> 128 floats
    const float* rt = (const float*)d_in[2];  // [64]
    const float* dt = (const float*)d_in[3];  // [64]
    float* out = (float*)d_out;

    dim3 grid(NN / (256 * 4), BB);
    fused_kernel<<<grid, 256>>>(x, W, rt, dt, out, out + (size_t)BB * NN);
}

// round 14
// speedup vs baseline: 1.1021x; 1.1021x over previous
#include <cuda_runtime.h>
#include <math_constants.h>

// Problem constants
#define BB 256
#define CC 8
#define MM 16
#define NN 4096
#define CM 128      // CC*MM
#define LEN_R 64
#define LEN_D 64
#define NBLK 4      // blocks along N per b (NN / 1024)

// Per-(b, n-block) partial argmax scratch + per-b ticket (device globals).
__device__ float g_pmax[BB][NBLK];
__device__ int   g_pidx[BB][NBLK];
__device__ int   g_ticket[BB];

// Fused kernel:
//  - outputs[b,n] = sum_k x[b,k,n] * W[k]  (k = c*M+m, 128 terms)
//  - simple float4 mainloop (ptxas schedules loads; 32 regs -> 8 blocks/SM)
//  - warp-shuffle partial argmax (first occurrence) -> scratch
//  - last block per b reduces partials, writes tail, resets ticket.
// __launch_bounds__(256, 8) pins the 8-blocks/SM operating point: R12/R13
// showed regs>32 -> occ 68% -> DRAM 75% -> +8us. Occupancy is the lever.
// tail layout (after outputs): d[B], r[B], d[B] (pytree leaves of (outputs, d, (r,d)))
__global__ __launch_bounds__(256, 8) void fused_kernel(
    const float* __restrict__ x, const float* __restrict__ W,
    const float* __restrict__ r_target, const float* __restrict__ d_target,
    float* __restrict__ out, float* __restrict__ tail)
{
    __shared__ float w[CM];
    int t = threadIdx.x;
    if (t < CM) w[t] = W[t];
    __syncthreads();

    int b  = blockIdx.y;
    int n4 = blockIdx.x * blockDim.x + t;          // float4 lane index in N/4
    const float4* xb = reinterpret_cast<const float4*>(x) + (size_t)b * CM * (NN / 4);

    float4 acc = make_float4(0.f, 0.f, 0.f, 0.f);
    #pragma unroll 16
    for (int k = 0; k < CM; k++) {
        float4 v = xb[(size_t)k * (NN / 4) + n4];
        float wk = w[k];
        acc.x += v.x * wk;
        acc.y += v.y * wk;
        acc.z += v.z * wk;
        acc.w += v.w * wk;
    }
    reinterpret_cast<float4*>(out + (size_t)b * NN)[n4] = acc;

    // Thread-local argmax over 4 lanes (strict > keeps first occurrence).
    int nbase = n4 * 4;
    float best = acc.x; int bidx = nbase;
    if (acc.y > best) { best = acc.y; bidx = nbase + 1; }
    if (acc.z > best) { best = acc.z; bidx = nbase + 2; }
    if (acc.w > best) { best = acc.w; bidx = nbase + 3; }

    // Warp reduction via shuffles; lower lane holds lower index, so strict >
    // with (==, oi < bidx) keeps first occurrence.
    #pragma unroll
    for (int off = 16; off > 0; off >>= 1) {
        float ov = __shfl_down_sync(0xffffffffu, best, off);
        int   oi = __shfl_down_sync(0xffffffffu, bidx, off);
        if (ov > best || (ov == best && oi < bidx)) { best = ov; bidx = oi; }
    }

    // 8 warp leaders -> smem, one barrier, warp 0 finishes.
    __shared__ float sv[8];
    __shared__ int   si[8];
    int warp = t >> 5, lane = t & 31;
    if (lane == 0) { sv[warp] = best; si[warp] = bidx; }
    __syncthreads();

    __shared__ int s_last;
    if (warp == 0) {
        float fb = (lane < 8) ? sv[lane] : -CUDART_INF_F;
        int   fi = (lane < 8) ? si[lane] : NN;      // sentinel index
        #pragma unroll
        for (int off = 4; off > 0; off >>= 1) {
            float ov = __shfl_down_sync(0xffffffffu, fb, off);
            int   oi = __shfl_down_sync(0xffffffffu, fi, off);
            if (ov > fb || (ov == fb && oi < fi)) { fb = ov; fi = oi; }
        }
        if (lane == 0) {
            g_pmax[b][blockIdx.x] = fb;
            g_pidx[b][blockIdx.x] = fi;
            __threadfence();
            int prev = atomicAdd(&g_ticket[b], 1);
            s_last = (prev == NBLK - 1);
        }
    }
    __syncthreads();

    if (s_last && t == 0) {
        // Winner re-reads all partials; volatile forces L2-visible loads
        // (L1 is per-SM and non-coherent for plain global loads).
        volatile float* pm = &g_pmax[b][0];
        volatile int*   pi = &g_pidx[b][0];
        float fb = pm[0];
        int   fi = pi[0];
        #pragma unroll
        for (int j = 1; j < NBLK; j++) {
            float v = pm[j]; int i = pi[j];
            if (v > fb || (v == fb && i < fi)) { fb = v; fi = i; }
        }
        int ri = fi / LEN_R;
        int di = fi - (fi / LEN_R) * LEN_D;
        // .astype(index.dtype) truncates toward zero; replicate via int cast.
        float rv = (float)(long long)(r_target[ri]);
        float dv = (float)(long long)(d_target[di]);
        tail[b]          = dv;  // leaf 2: d
        tail[BB + b]     = rv;  // leaf 3: r
        tail[2 * BB + b] = dv;  // leaf 4: d
        g_ticket[b] = 0;       // reset for next graph replay (deterministic)
    }
}

extern "C" void kernel_launch(void* const* d_in, const int* in_sizes, int n_in,
                              void* d_out, int out_size)
{
    const float* x  = (const float*)d_in[0];  // [B, C, M, N]
    const float* W  = (const float*)d_in[1];  // [1, C, M, 1] -> 128 floats
    const float* rt = (const float*)d_in[2];  // [64]
    const float* dt = (const float*)d_in[3];  // [64]
    float* out = (float*)d_out;

    dim3 grid(NN / (256 * 4), BB);
    fused_kernel<<<grid, 256>>>(x, W, rt, dt, out, out + (size_t)BB * NN);
}

// round 15
// speedup vs baseline: 1.1025x; 1.0004x over previous
#include <cuda_runtime.h>
#include <math_constants.h>

// Problem constants
#define BB 256
#define CC 8
#define MM 16
#define NN 4096
#define CM 128      // CC*MM
#define LEN_R 64
#define LEN_D 64
#define NBLK 4      // blocks along N per b (NN / 1024)

// Per-(b, n-block) partial argmax scratch + per-b ticket (device globals).
__device__ float g_pmax[BB][NBLK];
__device__ int   g_pidx[BB][NBLK];
__device__ int   g_ticket[BB];

// Fused kernel:
//  - outputs[b,n] = sum_k x[b,k,n] * W[k]  (k = c*M+m, 128 terms)
//  - simple float4 mainloop, unroll-32 window (ptxas front-batches loads
//    within the pinned 32-reg budget -> higher MLP_eff)
//  - warp-shuffle partial argmax (first occurrence) -> scratch
//  - last block per b reduces partials, writes tail, resets ticket.
// __launch_bounds__(256, 8) pins 8 blocks/SM: R12/R13 showed regs>32 ->
// occ 68% -> DRAM 75% -> +8us. Occupancy is the lever; hold it fixed.
// tail layout (after outputs): d[B], r[B], d[B] (pytree leaves of (outputs, d, (r,d)))
__global__ __launch_bounds__(256, 8) void fused_kernel(
    const float* __restrict__ x, const float* __restrict__ W,
    const float* __restrict__ r_target, const float* __restrict__ d_target,
    float* __restrict__ out, float* __restrict__ tail)
{
    __shared__ float w[CM];
    int t = threadIdx.x;
    if (t < CM) w[t] = W[t];
    __syncthreads();

    int b  = blockIdx.y;
    int n4 = blockIdx.x * blockDim.x + t;          // float4 lane index in N/4
    const float4* xb = reinterpret_cast<const float4*>(x) + (size_t)b * CM * (NN / 4);

    float4 acc = make_float4(0.f, 0.f, 0.f, 0.f);
    #pragma unroll 32
    for (int k = 0; k < CM; k++) {
        float4 v = xb[(size_t)k * (NN / 4) + n4];
        float wk = w[k];
        acc.x += v.x * wk;
        acc.y += v.y * wk;
        acc.z += v.z * wk;
        acc.w += v.w * wk;
    }
    reinterpret_cast<float4*>(out + (size_t)b * NN)[n4] = acc;

    // Thread-local argmax over 4 lanes (strict > keeps first occurrence).
    int nbase = n4 * 4;
    float best = acc.x; int bidx = nbase;
    if (acc.y > best) { best = acc.y; bidx = nbase + 1; }
    if (acc.z > best) { best = acc.z; bidx = nbase + 2; }
    if (acc.w > best) { best = acc.w; bidx = nbase + 3; }

    // Warp reduction via shuffles; lower lane holds lower index, so strict >
    // with (==, oi < bidx) keeps first occurrence.
    #pragma unroll
    for (int off = 16; off > 0; off >>= 1) {
        float ov = __shfl_down_sync(0xffffffffu, best, off);
        int   oi = __shfl_down_sync(0xffffffffu, bidx, off);
        if (ov > best || (ov == best && oi < bidx)) { best = ov; bidx = oi; }
    }

    // 8 warp leaders -> smem, one barrier, warp 0 finishes.
    __shared__ float sv[8];
    __shared__ int   si[8];
    int warp = t >> 5, lane = t & 31;
    if (lane == 0) { sv[warp] = best; si[warp] = bidx; }
    __syncthreads();

    __shared__ int s_last;
    if (warp == 0) {
        float fb = (lane < 8) ? sv[lane] : -CUDART_INF_F;
        int   fi = (lane < 8) ? si[lane] : NN;      // sentinel index
        #pragma unroll
        for (int off = 4; off > 0; off >>= 1) {
            float ov = __shfl_down_sync(0xffffffffu, fb, off);
            int   oi = __shfl_down_sync(0xffffffffu, fi, off);
            if (ov > fb || (ov == fb && oi < fi)) { fb = ov; fi = oi; }
        }
        if (lane == 0) {
            g_pmax[b][blockIdx.x] = fb;
            g_pidx[b][blockIdx.x] = fi;
            __threadfence();
            int prev = atomicAdd(&g_ticket[b], 1);
            s_last = (prev == NBLK - 1);
        }
    }
    __syncthreads();

    if (s_last && t == 0) {
        // Winner re-reads all partials; volatile forces L2-visible loads
        // (L1 is per-SM and non-coherent for plain global loads).
        volatile float* pm = &g_pmax[b][0];
        volatile int*   pi = &g_pidx[b][0];
        float fb = pm[0];
        int   fi = pi[0];
        #pragma unroll
        for (int j = 1; j < NBLK; j++) {
            float v = pm[j]; int i = pi[j];
            if (v > fb || (v == fb && i < fi)) { fb = v; fi = i; }
        }
        int ri = fi / LEN_R;
        int di = fi - (fi / LEN_R) * LEN_D;
        // .astype(index.dtype) truncates toward zero; replicate via int cast.
        float rv = (float)(long long)(r_target[ri]);
        float dv = (float)(long long)(d_target[di]);
        tail[b]          = dv;  // leaf 2: d
        tail[BB + b]     = rv;  // leaf 3: r
        tail[2 * BB + b] = dv;  // leaf 4: d
        g_ticket[b] = 0;       // reset for next graph replay (deterministic)
    }
}

extern "C" void kernel_launch(void* const* d_in, const int* in_sizes, int n_in,
                              void* d_out, int out_size)
{
    const float* x  = (const float*)d_in[0];  // [B, C, M, N]
    const float* W  = (const float*)d_in[1];  // [1, C, M, 1] -> 128 floats
    const float* rt = (const float*)d_in[2];  // [64]
    const float* dt = (const float*)d_in[3];  // [64]
    float* out = (float*)d_out;

    dim3 grid(NN / (256 * 4), BB);
    fused_kernel<<<grid, 256>>>(x, W, rt, dt, out, out + (size_t)BB * NN);
}